// round 14
// baseline (speedup 1.0000x reference)
#include <cuda_runtime.h>
#include <cuda_bf16.h>

// Sorted segment-sum: values (N, 256) fp32, segment_ids (N) sorted int32 in [0, B),
// out (B, 256) fp32.  DRAM-bound streaming kernel at the measured optimum:
// RPB=128 self-balancing blocks (grid=8192), float4 streaming loads with 8-way
// front-batching (MLP), register accumulation, rare vectorized-REDG flushes.
// Blocks entirely inside one segment (~94% at avg seglen 2048) take a
// check-free pure-streaming path. Measured: ~7.3 TB/s (91-93% of spec HBM);
// run-to-run bench variance is ~±1.5us around a ~149us mean.

#define C_COLS   256
#define CV       64      // float4 per row (256 floats)
#define RPB      128     // rows per block (measured optimum; divides N exactly)
#define UNR      8       // independent row-loads per thread per iteration (MLP)

// Vectorized fire-and-forget global reduction: one REDG.128.
__device__ __forceinline__ void red_add_v4(float* addr, float4 v) {
    asm volatile("red.global.add.v4.f32 [%0], {%1, %2, %3, %4};"
                 :: "l"(addr), "f"(v.x), "f"(v.y), "f"(v.z), "f"(v.w)
                 : "memory");
}

__global__ __launch_bounds__(256)
void segsum_kernel(const float4* __restrict__ vals,
                   const int*    __restrict__ seg,
                   float*        __restrict__ out,
                   int n)
{
    const int col = threadIdx.x;   // 0..63  (float4 column group)
    const int y   = threadIdx.y;   // 0..3   (row sub-stream)

    const int row0 = blockIdx.x * RPB;
    int rows = n - row0;
    if (rows > RPB) rows = RPB;

    float4 acc = make_float4(0.f, 0.f, 0.f, 0.f);

    if (rows == RPB) {
        const int s_first = __ldg(&seg[row0]);
        const int s_last  = __ldg(&seg[row0 + RPB - 1]);

        if (s_first == s_last) {
            // ---- uniform-segment fast path: pure streaming accumulate ----
            #pragma unroll 1
            for (int r = y; r < RPB; r += 4 * UNR) {
                float4 buf[UNR];
                #pragma unroll
                for (int u = 0; u < UNR; u++)
                    buf[u] = __ldcs(&vals[(size_t)(row0 + r + 4 * u) * CV + col]);
                #pragma unroll
                for (int u = 0; u < UNR; u++) {
                    acc.x += buf[u].x;
                    acc.y += buf[u].y;
                    acc.z += buf[u].z;
                    acc.w += buf[u].w;
                }
            }
            red_add_v4(out + (size_t)s_first * C_COLS + col * 4, acc);
            return;
        }

        // ---- boundary block: per-row segment tracking ----
        int cur = __ldg(&seg[row0 + y]);
        #pragma unroll 1
        for (int r = y; r < RPB; r += 4 * UNR) {
            int sb[UNR];
            #pragma unroll
            for (int u = 0; u < UNR; u++)
                sb[u] = __ldg(&seg[row0 + r + 4 * u]);
            float4 buf[UNR];
            #pragma unroll
            for (int u = 0; u < UNR; u++)
                buf[u] = __ldcs(&vals[(size_t)(row0 + r + 4 * u) * CV + col]);

            #pragma unroll
            for (int u = 0; u < UNR; u++) {
                if (sb[u] != cur) {
                    red_add_v4(out + (size_t)cur * C_COLS + col * 4, acc);
                    acc = make_float4(0.f, 0.f, 0.f, 0.f);
                    cur = sb[u];
                }
                acc.x += buf[u].x;
                acc.y += buf[u].y;
                acc.z += buf[u].z;
                acc.w += buf[u].w;
            }
        }
        red_add_v4(out + (size_t)cur * C_COLS + col * 4, acc);
        return;
    }

    // ---- ragged tail block (n not multiple of RPB) ----
    int cur = (y < rows) ? __ldg(&seg[row0 + y]) : -1;
    for (int r = y; r < rows; r += 4) {
        float4 v = __ldcs(&vals[(size_t)(row0 + r) * CV + col]);
        const int s = __ldg(&seg[row0 + r]);
        if (s != cur) {
            red_add_v4(out + (size_t)cur * C_COLS + col * 4, acc);
            acc = make_float4(0.f, 0.f, 0.f, 0.f);
            cur = s;
        }
        acc.x += v.x;
        acc.y += v.y;
        acc.z += v.z;
        acc.w += v.w;
    }
    if (cur >= 0)
        red_add_v4(out + (size_t)cur * C_COLS + col * 4, acc);
}

extern "C" void kernel_launch(void* const* d_in, const int* in_sizes, int n_in,
                              void* d_out, int out_size)
{
    const float* values = (const float*)d_in[0];
    const int*   segids = (const int*)d_in[1];
    float* out = (float*)d_out;

    const int n = in_sizes[1];   // number of rows

    // Output is poisoned; zero it (graph-capturable memset node), flushes
    // accumulate on top.
    cudaMemsetAsync(out, 0, (size_t)out_size * sizeof(float));

    dim3 block(64, 4);
    int grid = (n + RPB - 1) / RPB;
    segsum_kernel<<<grid, block>>>((const float4*)values, segids, out, n);
}

// round 15
// speedup vs baseline: 1.0136x; 1.0136x over previous
#include <cuda_runtime.h>
#include <cuda_bf16.h>

// Sorted segment-sum: values (N, 256) fp32, segment_ids (N) sorted int32 in [0, B),
// out (B, 256) fp32.  DRAM-bound streaming kernel at the measured optimum:
// RPB=128 self-balancing blocks (grid=8192), float4 streaming loads with 8-way
// front-batching (MLP), register accumulation, rare vectorized-REDG flushes.
// Blocks entirely inside one segment (~94% at avg seglen 2048) take a
// check-free pure-streaming path. Measured: ~7.3 TB/s (91-93% of spec HBM);
// run-to-run bench variance is ~±1.5us around a ~149us mean.

#define C_COLS   256
#define CV       64      // float4 per row (256 floats)
#define RPB      128     // rows per block (measured optimum; divides N exactly)
#define UNR      8       // independent row-loads per thread per iteration (MLP)

// Vectorized fire-and-forget global reduction: one REDG.128.
__device__ __forceinline__ void red_add_v4(float* addr, float4 v) {
    asm volatile("red.global.add.v4.f32 [%0], {%1, %2, %3, %4};"
                 :: "l"(addr), "f"(v.x), "f"(v.y), "f"(v.z), "f"(v.w)
                 : "memory");
}

__global__ __launch_bounds__(256)
void segsum_kernel(const float4* __restrict__ vals,
                   const int*    __restrict__ seg,
                   float*        __restrict__ out,
                   int n)
{
    const int col = threadIdx.x;   // 0..63  (float4 column group)
    const int y   = threadIdx.y;   // 0..3   (row sub-stream)

    const int row0 = blockIdx.x * RPB;
    int rows = n - row0;
    if (rows > RPB) rows = RPB;

    float4 acc = make_float4(0.f, 0.f, 0.f, 0.f);

    if (rows == RPB) {
        const int s_first = __ldg(&seg[row0]);
        const int s_last  = __ldg(&seg[row0 + RPB - 1]);

        if (s_first == s_last) {
            // ---- uniform-segment fast path: pure streaming accumulate ----
            #pragma unroll 1
            for (int r = y; r < RPB; r += 4 * UNR) {
                float4 buf[UNR];
                #pragma unroll
                for (int u = 0; u < UNR; u++)
                    buf[u] = __ldcs(&vals[(size_t)(row0 + r + 4 * u) * CV + col]);
                #pragma unroll
                for (int u = 0; u < UNR; u++) {
                    acc.x += buf[u].x;
                    acc.y += buf[u].y;
                    acc.z += buf[u].z;
                    acc.w += buf[u].w;
                }
            }
            red_add_v4(out + (size_t)s_first * C_COLS + col * 4, acc);
            return;
        }

        // ---- boundary block: per-row segment tracking ----
        int cur = __ldg(&seg[row0 + y]);
        #pragma unroll 1
        for (int r = y; r < RPB; r += 4 * UNR) {
            int sb[UNR];
            #pragma unroll
            for (int u = 0; u < UNR; u++)
                sb[u] = __ldg(&seg[row0 + r + 4 * u]);
            float4 buf[UNR];
            #pragma unroll
            for (int u = 0; u < UNR; u++)
                buf[u] = __ldcs(&vals[(size_t)(row0 + r + 4 * u) * CV + col]);

            #pragma unroll
            for (int u = 0; u < UNR; u++) {
                if (sb[u] != cur) {
                    red_add_v4(out + (size_t)cur * C_COLS + col * 4, acc);
                    acc = make_float4(0.f, 0.f, 0.f, 0.f);
                    cur = sb[u];
                }
                acc.x += buf[u].x;
                acc.y += buf[u].y;
                acc.z += buf[u].z;
                acc.w += buf[u].w;
            }
        }
        red_add_v4(out + (size_t)cur * C_COLS + col * 4, acc);
        return;
    }

    // ---- ragged tail block (n not multiple of RPB) ----
    int cur = (y < rows) ? __ldg(&seg[row0 + y]) : -1;
    for (int r = y; r < rows; r += 4) {
        float4 v = __ldcs(&vals[(size_t)(row0 + r) * CV + col]);
        const int s = __ldg(&seg[row0 + r]);
        if (s != cur) {
            red_add_v4(out + (size_t)cur * C_COLS + col * 4, acc);
            acc = make_float4(0.f, 0.f, 0.f, 0.f);
            cur = s;
        }
        acc.x += v.x;
        acc.y += v.y;
        acc.z += v.z;
        acc.w += v.w;
    }
    if (cur >= 0)
        red_add_v4(out + (size_t)cur * C_COLS + col * 4, acc);
}

extern "C" void kernel_launch(void* const* d_in, const int* in_sizes, int n_in,
                              void* d_out, int out_size)
{
    const float* values = (const float*)d_in[0];
    const int*   segids = (const int*)d_in[1];
    float* out = (float*)d_out;

    const int n = in_sizes[1];   // number of rows

    // Output is poisoned; zero it (graph-capturable memset node), flushes
    // accumulate on top.
    cudaMemsetAsync(out, 0, (size_t)out_size * sizeof(float));

    dim3 block(64, 4);
    int grid = (n + RPB - 1) / RPB;
    segsum_kernel<<<grid, block>>>((const float4*)values, segids, out, n);
}